// round 9
// baseline (speedup 1.0000x reference)
#include <cuda_runtime.h>
#include <cstdint>
#include <math.h>

#define NB    128
#define H     128
#define NPG   8
#define BT    3
#define AA    243
#define PAIRS 192
#define TPB   256
#define ABST  132

typedef unsigned long long u64;
typedef unsigned int u32;

__device__ __forceinline__ u64 pack2(float lo, float hi) {
    u64 r; asm("mov.b64 %0, {%1, %2};" : "=l"(r) : "f"(lo), "f"(hi)); return r;
}
__device__ __forceinline__ void fma2(u64& d, u64 a, u64 b) {
    asm("fma.rn.f32x2 %0, %1, %2, %0;" : "+l"(d) : "l"(a), "l"(b));
}
__device__ __forceinline__ float2 unpack2(u64 v) {
    float2 f; asm("mov.b64 {%0, %1}, %2;" : "=f"(f.x), "=f"(f.y) : "l"(v)); return f;
}
__device__ __forceinline__ u32 smem_u32(const void* p) {
    u32 a;
    asm("{ .reg .u64 t; cvta.to.shared.u64 t, %1; cvt.u32.u64 %0, t; }" : "=r"(a) : "l"(p));
    return a;
}

__global__ __launch_bounds__(TPB, 2) __cluster_dims__(2, 1, 1)
void fused_apm_kernel(const float* __restrict__ nf,      // (1024,128)
                      const float* __restrict__ mask,    // (128,243)
                      const float* __restrict__ Wfcv1,   // (128,64)
                      const float* __restrict__ bfcv1,   // (64)
                      const float* __restrict__ Wfcv2,   // (64,1)
                      const float* __restrict__ bfcv2,   // (1)
                      const float* __restrict__ Wa2,     // (256,128)
                      const float* __restrict__ ba2,     // (128)
                      const float* __restrict__ Wfin,    // (128,3)
                      const float* __restrict__ bfin,    // (3)
                      const int*   __restrict__ idxmask, // (128,243)
                      float* __restrict__ out)           // probs[128*243] ++ readout[128]
{
    const int b = blockIdx.x >> 1;
    const int t = threadIdx.x;
    u32 rank;
    asm("mov.u32 %0, %%cluster_ctarank;" : "=r"(rank));
    const int grp = (int)rank;                 // rank0 -> Ai (grp0), rank1 -> Bj (grp1)

    __shared__ __align__(16) u64   ps[H][4];          // [c][node-pair]
    __shared__ __align__(16) float ABloc[NPG][ABST];  // this rank's half
    __shared__ __align__(16) float ABpeer[NPG][ABST]; // peer's half (DSMEM copy)
    __shared__ __align__(16) float sWfT[BT][H];
    __shared__ __align__(16) float sba[H];
    __shared__ __align__(16) float ssum[H];
    __shared__ float sc[PAIRS];
    __shared__ int   sidx[AA];
    __shared__ float smk[AA];
    __shared__ float red[2];

    // ---- entry: role-specific cold loads first ----
    if (rank == 0) {
        if (t < AA) {
            sidx[t] = idxmask[b * AA + t];
            smk[t]  = mask[b * AA + t];
        }
    } else {
        if (t < H) {
            float a = 0.f;
            #pragma unroll
            for (int n = 0; n < NPG; n++) a += nf[(b * NPG + n) * H + t];
            ssum[t] = a;
        }
    }

    // GEMM mapping + first W batch before barrier
    const int h = t & 127;
    const int X = t >> 7;                      // node quad 4X..4X+3
    const float* Wp = Wa2 + grp * H * H + h;
    float Wr[32];
    #pragma unroll
    for (int i = 0; i < 32; i++) Wr[i] = Wp[i * H];

    // ---- stage node features (one STS.128 per thread) ----
    {
        const int c = t & 127;
        float v0 = fmaxf(nf[(b * NPG + 4 * X + 0) * H + c], 0.f);
        float v1 = fmaxf(nf[(b * NPG + 4 * X + 1) * H + c], 0.f);
        float v2 = fmaxf(nf[(b * NPG + 4 * X + 2) * H + c], 0.f);
        float v3 = fmaxf(nf[(b * NPG + 4 * X + 3) * H + c], 0.f);
        ulonglong2 pp;
        pp.x = pack2(v0, v1);
        pp.y = pack2(v2, v3);
        *reinterpret_cast<ulonglong2*>(&ps[c][X * 2]) = pp;
    }
    // small weights
    #pragma unroll
    for (int idx = t; idx < H * BT + H; idx += TPB) {
        if (idx < H * BT) {
            int hh = idx & 127, k = idx >> 7;
            sWfT[k][hh] = Wfin[hh * BT + k];
        } else {
            sba[idx - H * BT] = ba2[idx - H * BT];
        }
    }
    __syncthreads();   // S1

    // ---- half-GEMM (this rank's grp only): 4 nodes/thread, full c ----
    {
        u64 acc0 = 0, acc1 = 0;                // pairs 2X, 2X+1
        #pragma unroll
        for (int batch = 0; batch < 4; batch++) {
            if (batch) {
                #pragma unroll
                for (int i = 0; i < 32; i++) Wr[i] = Wp[(batch * 32 + i) * H];
            }
            #pragma unroll
            for (int cc = 0; cc < 32; cc++) {
                const int c = batch * 32 + cc;
                u64 wp = pack2(Wr[cc], Wr[cc]);
                ulonglong2 q = *reinterpret_cast<const ulonglong2*>(&ps[c][X * 2]);
                fma2(acc0, q.x, wp);
                fma2(acc1, q.y, wp);
            }
        }
        float2 f;
        f = unpack2(acc0); ABloc[4 * X + 0][h] = f.x; ABloc[4 * X + 1][h] = f.y;
        f = unpack2(acc1); ABloc[4 * X + 2][h] = f.x; ABloc[4 * X + 3][h] = f.y;
    }

    // ---- cluster sync: both halves ready ----
    asm volatile("barrier.cluster.arrive.aligned;" ::: "memory");
    asm volatile("barrier.cluster.wait.aligned;"   ::: "memory");

    // ---- copy peer's AB half into local smem via DSMEM ----
    {
        const u32 myab = smem_u32(&ABloc[0][0]);
        const u32 peer = rank ^ 1u;
        float4* dst = reinterpret_cast<float4*>(&ABpeer[0][0]);
        #pragma unroll
        for (int idx = t; idx < (NPG * ABST) / 4; idx += TPB) {
            u32 raddr;
            asm("mapa.shared::cluster.u32 %0, %1, %2;"
                : "=r"(raddr) : "r"(myab + idx * 16), "r"(peer));
            float4 v;
            asm volatile("ld.shared::cluster.v4.f32 {%0,%1,%2,%3}, [%4];"
                         : "=f"(v.x), "=f"(v.y), "=f"(v.z), "=f"(v.w) : "r"(raddr));
            dst[idx] = v;
        }
    }

    // ---- cluster sync: copy done everywhere (also exit-safety) ----
    asm volatile("barrier.cluster.arrive.aligned;" ::: "memory");
    asm volatile("barrier.cluster.wait.aligned;"   ::: "memory");

    // ---- pair scores (both ranks compute all 192; t<192, 1 thread/score) ----
    {
        const float (*Arows)[ABST] = (grp == 0) ? ABloc : ABpeer;
        const float (*Brows)[ABST] = (grp == 0) ? ABpeer : ABloc;
        if (t < PAIRS) {
            const int k = t >> 6;
            const int p = t & 63;
            const int i = p >> 3, j = p & 7;
            const float4* A4 = reinterpret_cast<const float4*>(Arows[i]);
            const float4* B4 = reinterpret_cast<const float4*>(Brows[j]);
            const float4* W4 = reinterpret_cast<const float4*>(sWfT[k]);
            const float4* Z4 = reinterpret_cast<const float4*>(sba);
            float acc0 = 0.f, acc1 = 0.f;
            #pragma unroll
            for (int q = 0; q < 32; q += 2) {
                float4 a, bb, w, z;
                a = A4[q]; bb = B4[q]; w = W4[q]; z = Z4[q];
                acc0 += fmaxf(a.x + bb.x + z.x, 0.f) * w.x
                      + fmaxf(a.y + bb.y + z.y, 0.f) * w.y
                      + fmaxf(a.z + bb.z + z.z, 0.f) * w.z
                      + fmaxf(a.w + bb.w + z.w, 0.f) * w.w;
                a = A4[q + 1]; bb = B4[q + 1]; w = W4[q + 1]; z = Z4[q + 1];
                acc1 += fmaxf(a.x + bb.x + z.x, 0.f) * w.x
                      + fmaxf(a.y + bb.y + z.y, 0.f) * w.y
                      + fmaxf(a.z + bb.z + z.z, 0.f) * w.z
                      + fmaxf(a.w + bb.w + z.w, 0.f) * w.w;
            }
            sc[p * BT + k] = acc0 + acc1 + bfin[k];
        } else if (rank == 1) {
            // readout MLP on rank1's warps 6-7
            const int j = t - PAIRS;           // 0..63
            const float4* S4 = reinterpret_cast<const float4*>(ssum);
            float acc0 = 0.f, acc1 = 0.f;
            #pragma unroll
            for (int q = 0; q < 32; q += 2) {
                float4 sv = S4[q];
                int c = q * 4;
                acc0 += sv.x * Wfcv1[(c + 0) * 64 + j] + sv.y * Wfcv1[(c + 1) * 64 + j]
                      + sv.z * Wfcv1[(c + 2) * 64 + j] + sv.w * Wfcv1[(c + 3) * 64 + j];
                sv = S4[q + 1];
                c = (q + 1) * 4;
                acc1 += sv.x * Wfcv1[(c + 0) * 64 + j] + sv.y * Wfcv1[(c + 1) * 64 + j]
                      + sv.z * Wfcv1[(c + 2) * 64 + j] + sv.w * Wfcv1[(c + 3) * 64 + j];
            }
            float hid = fmaxf(acc0 + acc1 + bfcv1[j], 0.f) * Wfcv2[j];
            #pragma unroll
            for (int off = 16; off > 0; off >>= 1)
                hid += __shfl_down_sync(0xffffffffu, hid, off);
            if ((t & 31) == 0) red[(t >> 5) - 6] = hid;
        }
    }
    __syncthreads();   // S3

    if (rank == 1) {
        if (t == 0) out[NB * AA + b] = red[0] + red[1] + bfcv2[0];
        return;
    }

    // ---- rank0 warp0: gather + softmax + probs ----
    if (t < 32) {
        float fv[8];
        #pragma unroll
        for (int q = 0; q < 8; q++) {
            int e = t + 32 * q;
            if (e < AA) {
                int im = sidx[e];
                fv[q] = ((im < PAIRS) ? sc[im] : 0.f) + smk[e];
            } else fv[q] = -INFINITY;
        }
        float m = fv[0];
        #pragma unroll
        for (int q = 1; q < 8; q++) m = fmaxf(m, fv[q]);
        #pragma unroll
        for (int off = 16; off > 0; off >>= 1)
            m = fmaxf(m, __shfl_xor_sync(0xffffffffu, m, off));
        float sr = 0.f;
        #pragma unroll
        for (int q = 0; q < 8; q++) {
            fv[q] = (fv[q] == -INFINITY) ? 0.f : __expf(fv[q] - m);
            sr += fv[q];
        }
        #pragma unroll
        for (int off = 16; off > 0; off >>= 1)
            sr += __shfl_xor_sync(0xffffffffu, sr, off);
        float inv = 1.f / sr;
        #pragma unroll
        for (int q = 0; q < 8; q++) {
            int e = t + 32 * q;
            if (e < AA) out[b * AA + e] = fv[q] * inv;
        }
    }
}

extern "C" void kernel_launch(void* const* d_in, const int* in_sizes, int n_in,
                              void* d_out, int out_size) {
    const float* nf     = (const float*)d_in[0];
    const float* mask   = (const float*)d_in[2];
    const float* Wfcv1  = (const float*)d_in[3];
    const float* bfcv1  = (const float*)d_in[4];
    const float* Wfcv2  = (const float*)d_in[5];
    const float* bfcv2  = (const float*)d_in[6];
    const float* Wa2    = (const float*)d_in[7];
    const float* ba2    = (const float*)d_in[8];
    const float* Wfin   = (const float*)d_in[9];
    const float* bfin   = (const float*)d_in[10];
    const int*   idxm   = (const int*)d_in[11];
    float* out = (float*)d_out;

    fused_apm_kernel<<<2 * NB, TPB>>>(nf, mask, Wfcv1, bfcv1, Wfcv2, bfcv2,
                                      Wa2, ba2, Wfin, bfin, idxm, out);
}